// round 3
// baseline (speedup 1.0000x reference)
#include <cuda_runtime.h>

// Fused transformer block, 2 query rows per thread, 2 batch elements per CTA.
// B=2048, T=128, DM=32, H=2, DK=16. grid=1024, block=128.

namespace {
constexpr int Bsz = 2048;
constexpr int T   = 128;
constexpr int DM  = 32;
constexpr int FF  = 128;
constexpr int KVS = 36;   // padded row stride for K/V

// shared layout (floats)
constexpr int OFF_W1 = 0;        // 4096 (aliases Wq|Wk|Wv = 3072 in phase A)
constexpr int OFF_W2 = 4096;     // 4096
constexpr int OFF_WO = 8192;     // 1024
constexpr int OFF_B  = 9216;     // 320: bo[32] b1[128] b2[32] g1[32] be1[32] g2[32] be2[32]
constexpr int OFF_KV = 9536;     // 2 local batches * (K 4608 + V 4608)
constexpr int SMEM_FLOATS = OFF_KV + 2 * 2 * T * KVS;  // 27968
constexpr int SMEM_BYTES  = SMEM_FLOATS * 4;           // 111872 -> 2 CTAs/SM
}

__device__ __forceinline__ void ln_row(float* x, const float* g, const float* be) {
    float mu = 0.f;
    #pragma unroll
    for (int d = 0; d < DM; d++) mu += x[d];
    mu *= (1.f / DM);
    float var = 0.f;
    #pragma unroll
    for (int d = 0; d < DM; d++) { float c = x[d] - mu; var = fmaf(c, c, var); }
    var *= (1.f / DM);
    float r = rsqrtf(var + 1e-5f);
    #pragma unroll
    for (int d = 0; d < DM; d++) x[d] = (x[d] - mu) * r * g[d] + be[d];
}

__global__ void __launch_bounds__(128, 2) block_kernel(
    const float* __restrict__ gx,
    const float* __restrict__ gWq, const float* __restrict__ gWk, const float* __restrict__ gWv,
    const float* __restrict__ gWo, const float* __restrict__ gbo,
    const float* __restrict__ gW1, const float* __restrict__ gb1,
    const float* __restrict__ gW2, const float* __restrict__ gb2,
    const float* __restrict__ gg1, const float* __restrict__ gbe1,
    const float* __restrict__ gg2, const float* __restrict__ gbe2,
    float* __restrict__ gout)
{
    extern __shared__ float sm[];
    float* sQKV = sm + OFF_W1;     // phase A
    float* sW1  = sm + OFF_W1;     // phase B
    float* sW2  = sm + OFF_W2;
    float* sWo  = sm + OFF_WO;
    float* sbo  = sm + OFF_B;
    float* sb1  = sm + OFF_B + 32;
    float* sb2  = sm + OFF_B + 160;
    float* sg1  = sm + OFF_B + 192;
    float* sbe1 = sm + OFF_B + 224;
    float* sg2  = sm + OFF_B + 256;
    float* sbe2 = sm + OFF_B + 288;

    const int tid  = threadIdx.x;
    const int wid  = tid >> 5;
    const int lane = tid & 31;
    const int bl   = wid >> 1;                       // local batch 0/1
    const int u    = ((wid & 1) << 5) | lane;        // 0..63
    const int r0   = 2 * u, r1 = 2 * u + 1;          // this thread's query rows
    const long gb  = (long)blockIdx.x * 2 + bl;      // global batch

    float* sK = sm + OFF_KV + bl * (2 * T * KVS);
    float* sV = sK + T * KVS;

    // ---- phase A cooperative loads ----
    {
        float4*       dq = (float4*)sQKV;
        const float4* s;
        s = (const float4*)gWq; for (int i = tid; i < 256;  i += 128) dq[i]       = s[i];
        s = (const float4*)gWk; for (int i = tid; i < 256;  i += 128) dq[256 + i] = s[i];
        s = (const float4*)gWv; for (int i = tid; i < 256;  i += 128) dq[512 + i] = s[i];
        float4* d2 = (float4*)sW2; s = (const float4*)gW2; for (int i = tid; i < 1024; i += 128) d2[i] = s[i];
        float4* d3 = (float4*)sWo; s = (const float4*)gWo; for (int i = tid; i < 256;  i += 128) d3[i] = s[i];
        if (tid < 32) {
            sbo[tid]  = gbo[tid];  sb2[tid]  = gb2[tid];
            sg1[tid]  = gg1[tid];  sbe1[tid] = gbe1[tid];
            sg2[tid]  = gg2[tid];  sbe2[tid] = gbe2[tid];
        }
        sb1[tid] = gb1[tid];
    }
    __syncthreads();

    // ---- load 2 x rows, LN1 ----
    float xa[DM], xb[DM];
    {
        const float4* pa = (const float4*)(gx + (gb * T + r0) * DM);
        const float4* pb = (const float4*)(gx + (gb * T + r1) * DM);
        #pragma unroll
        for (int i = 0; i < 8; i++) {
            float4 v = pa[i]; xa[4*i] = v.x; xa[4*i+1] = v.y; xa[4*i+2] = v.z; xa[4*i+3] = v.w;
            float4 w = pb[i]; xb[4*i] = w.x; xb[4*i+1] = w.y; xb[4*i+2] = w.z; xb[4*i+3] = w.w;
        }
        ln_row(xa, sg1, sbe1);
        ln_row(xb, sg1, sbe1);
    }

    // ---- q/k/v projections, weight loads shared across the 2 rows ----
    float qa[DM], qb[DM];
    #pragma unroll
    for (int g = 0; g < 8; g++) {
        const float* wp = sQKV + (g >> 2) * 512 + (g & 3) * 4;
        float a0=0.f,a1=0.f,a2=0.f,a3=0.f, b0=0.f,b1v=0.f,b2v=0.f,b3=0.f;
        #pragma unroll
        for (int d = 0; d < DM; d++) {
            float4 w = *(const float4*)(wp + d * 16);
            a0 = fmaf(xa[d], w.x, a0); a1  = fmaf(xa[d], w.y, a1);
            a2 = fmaf(xa[d], w.z, a2); a3  = fmaf(xa[d], w.w, a3);
            b0 = fmaf(xb[d], w.x, b0); b1v = fmaf(xb[d], w.y, b1v);
            b2v= fmaf(xb[d], w.z, b2v); b3 = fmaf(xb[d], w.w, b3);
        }
        qa[4*g]=a0; qa[4*g+1]=a1; qa[4*g+2]=a2; qa[4*g+3]=a3;
        qb[4*g]=b0; qb[4*g+1]=b1v; qb[4*g+2]=b2v; qb[4*g+3]=b3;
    }
    #pragma unroll
    for (int g = 0; g < 8; g++) {    // k rows
        const float* wp = sQKV + 1024 + (g >> 2) * 512 + (g & 3) * 4;
        float a0=0.f,a1=0.f,a2=0.f,a3=0.f, b0=0.f,b1v=0.f,b2v=0.f,b3=0.f;
        #pragma unroll
        for (int d = 0; d < DM; d++) {
            float4 w = *(const float4*)(wp + d * 16);
            a0 = fmaf(xa[d], w.x, a0); a1  = fmaf(xa[d], w.y, a1);
            a2 = fmaf(xa[d], w.z, a2); a3  = fmaf(xa[d], w.w, a3);
            b0 = fmaf(xb[d], w.x, b0); b1v = fmaf(xb[d], w.y, b1v);
            b2v= fmaf(xb[d], w.z, b2v); b3 = fmaf(xb[d], w.w, b3);
        }
        *(float4*)(sK + r0 * KVS + 4 * g) = make_float4(a0, a1, a2, a3);
        *(float4*)(sK + r1 * KVS + 4 * g) = make_float4(b0, b1v, b2v, b3);
    }
    #pragma unroll
    for (int g = 0; g < 8; g++) {    // v rows
        const float* wp = sQKV + 2048 + (g >> 2) * 512 + (g & 3) * 4;
        float a0=0.f,a1=0.f,a2=0.f,a3=0.f, b0=0.f,b1v=0.f,b2v=0.f,b3=0.f;
        #pragma unroll
        for (int d = 0; d < DM; d++) {
            float4 w = *(const float4*)(wp + d * 16);
            a0 = fmaf(xa[d], w.x, a0); a1  = fmaf(xa[d], w.y, a1);
            a2 = fmaf(xa[d], w.z, a2); a3  = fmaf(xa[d], w.w, a3);
            b0 = fmaf(xb[d], w.x, b0); b1v = fmaf(xb[d], w.y, b1v);
            b2v= fmaf(xb[d], w.z, b2v); b3 = fmaf(xb[d], w.w, b3);
        }
        *(float4*)(sV + r0 * KVS + 4 * g) = make_float4(a0, a1, a2, a3);
        *(float4*)(sV + r1 * KVS + 4 * g) = make_float4(b0, b1v, b2v, b3);
    }
    __syncthreads();   // k,v visible; sQKV free

    // stage W1 over attention (disjoint from sK/sV; fenced before FFN)
    {
        const float4* s = (const float4*)gW1;
        float4*       d = (float4*)sW1;
        for (int i = tid; i < 1024; i += 128) d[i] = s[i];
    }

    // ---- causal attention, 2 rows/thread, streaming softmax (no max shift: |score|<=~32) ----
    float aa[DM], ab[DM];
    #pragma unroll
    for (int j = 0; j < DM; j++) { aa[j] = 0.f; ab[j] = 0.f; }
    float l0a = 0.f, l1a = 0.f, l0b = 0.f, l1b = 0.f;

    for (int s = 0; s <= r0; s++) {
        const float* kp = sK + s * KVS;
        float4 k0 = *(const float4*)(kp +  0);
        float4 k1 = *(const float4*)(kp +  4);
        float4 k2 = *(const float4*)(kp +  8);
        float4 k3 = *(const float4*)(kp + 12);
        float4 k4 = *(const float4*)(kp + 16);
        float4 k5 = *(const float4*)(kp + 20);
        float4 k6 = *(const float4*)(kp + 24);
        float4 k7 = *(const float4*)(kp + 28);

        float p, q2;
        // row a, head 0
        p  = qa[0]*k0.x;          q2 = qa[1]*k0.y;
        p  = fmaf(qa[2],k0.z,p);  q2 = fmaf(qa[3],k0.w,q2);
        p  = fmaf(qa[4],k1.x,p);  q2 = fmaf(qa[5],k1.y,q2);
        p  = fmaf(qa[6],k1.z,p);  q2 = fmaf(qa[7],k1.w,q2);
        p  = fmaf(qa[8],k2.x,p);  q2 = fmaf(qa[9],k2.y,q2);
        p  = fmaf(qa[10],k2.z,p); q2 = fmaf(qa[11],k2.w,q2);
        p  = fmaf(qa[12],k3.x,p); q2 = fmaf(qa[13],k3.y,q2);
        p  = fmaf(qa[14],k3.z,p); q2 = fmaf(qa[15],k3.w,q2);
        float d0a = p + q2;
        // row a, head 1
        p  = qa[16]*k4.x;          q2 = qa[17]*k4.y;
        p  = fmaf(qa[18],k4.z,p);  q2 = fmaf(qa[19],k4.w,q2);
        p  = fmaf(qa[20],k5.x,p);  q2 = fmaf(qa[21],k5.y,q2);
        p  = fmaf(qa[22],k5.z,p);  q2 = fmaf(qa[23],k5.w,q2);
        p  = fmaf(qa[24],k6.x,p);  q2 = fmaf(qa[25],k6.y,q2);
        p  = fmaf(qa[26],k6.z,p);  q2 = fmaf(qa[27],k6.w,q2);
        p  = fmaf(qa[28],k7.x,p);  q2 = fmaf(qa[29],k7.y,q2);
        p  = fmaf(qa[30],k7.z,p);  q2 = fmaf(qa[31],k7.w,q2);
        float d1a = p + q2;
        // row b, head 0
        p  = qb[0]*k0.x;          q2 = qb[1]*k0.y;
        p  = fmaf(qb[2],k0.z,p);  q2 = fmaf(qb[3],k0.w,q2);
        p  = fmaf(qb[4],k1.x,p);  q2 = fmaf(qb[5],k1.y,q2);
        p  = fmaf(qb[6],k1.z,p);  q2 = fmaf(qb[7],k1.w,q2);
        p  = fmaf(qb[8],k2.x,p);  q2 = fmaf(qb[9],k2.y,q2);
        p  = fmaf(qb[10],k2.z,p); q2 = fmaf(qb[11],k2.w,q2);
        p  = fmaf(qb[12],k3.x,p); q2 = fmaf(qb[13],k3.y,q2);
        p  = fmaf(qb[14],k3.z,p); q2 = fmaf(qb[15],k3.w,q2);
        float d0b = p + q2;
        // row b, head 1
        p  = qb[16]*k4.x;          q2 = qb[17]*k4.y;
        p  = fmaf(qb[18],k4.z,p);  q2 = fmaf(qb[19],k4.w,q2);
        p  = fmaf(qb[20],k5.x,p);  q2 = fmaf(qb[21],k5.y,q2);
        p  = fmaf(qb[22],k5.z,p);  q2 = fmaf(qb[23],k5.w,q2);
        p  = fmaf(qb[24],k6.x,p);  q2 = fmaf(qb[25],k6.y,q2);
        p  = fmaf(qb[26],k6.z,p);  q2 = fmaf(qb[27],k6.w,q2);
        p  = fmaf(qb[28],k7.x,p);  q2 = fmaf(qb[29],k7.y,q2);
        p  = fmaf(qb[30],k7.z,p);  q2 = fmaf(qb[31],k7.w,q2);
        float d1b = p + q2;

        float p0a = __expf(d0a), p1a = __expf(d1a);
        float p0b = __expf(d0b), p1b = __expf(d1b);
        l0a += p0a; l1a += p1a; l0b += p0b; l1b += p1b;

        const float* vp = sV + s * KVS;
        #pragma unroll
        for (int g = 0; g < 4; g++) {
            float4 vv = *(const float4*)(vp + 4 * g);
            aa[4*g]   = fmaf(p0a, vv.x, aa[4*g]);
            aa[4*g+1] = fmaf(p0a, vv.y, aa[4*g+1]);
            aa[4*g+2] = fmaf(p0a, vv.z, aa[4*g+2]);
            aa[4*g+3] = fmaf(p0a, vv.w, aa[4*g+3]);
            ab[4*g]   = fmaf(p0b, vv.x, ab[4*g]);
            ab[4*g+1] = fmaf(p0b, vv.y, ab[4*g+1]);
            ab[4*g+2] = fmaf(p0b, vv.z, ab[4*g+2]);
            ab[4*g+3] = fmaf(p0b, vv.w, ab[4*g+3]);
        }
        #pragma unroll
        for (int g = 4; g < 8; g++) {
            float4 vv = *(const float4*)(vp + 4 * g);
            aa[4*g]   = fmaf(p1a, vv.x, aa[4*g]);
            aa[4*g+1] = fmaf(p1a, vv.y, aa[4*g+1]);
            aa[4*g+2] = fmaf(p1a, vv.z, aa[4*g+2]);
            aa[4*g+3] = fmaf(p1a, vv.w, aa[4*g+3]);
            ab[4*g]   = fmaf(p1b, vv.x, ab[4*g]);
            ab[4*g+1] = fmaf(p1b, vv.y, ab[4*g+1]);
            ab[4*g+2] = fmaf(p1b, vv.z, ab[4*g+2]);
            ab[4*g+3] = fmaf(p1b, vv.w, ab[4*g+3]);
        }
    }

    // extra diagonal step for row b: s = r1
    {
        const float* kp = sK + r1 * KVS;
        float p, q2, r;
        float4 k0 = *(const float4*)(kp +  0);
        float4 k1 = *(const float4*)(kp +  4);
        float4 k2 = *(const float4*)(kp +  8);
        float4 k3 = *(const float4*)(kp + 12);
        p  = qb[0]*k0.x;          q2 = qb[1]*k0.y;
        p  = fmaf(qb[2],k0.z,p);  q2 = fmaf(qb[3],k0.w,q2);
        p  = fmaf(qb[4],k1.x,p);  q2 = fmaf(qb[5],k1.y,q2);
        p  = fmaf(qb[6],k1.z,p);  q2 = fmaf(qb[7],k1.w,q2);
        p  = fmaf(qb[8],k2.x,p);  q2 = fmaf(qb[9],k2.y,q2);
        p  = fmaf(qb[10],k2.z,p); q2 = fmaf(qb[11],k2.w,q2);
        p  = fmaf(qb[12],k3.x,p); q2 = fmaf(qb[13],k3.y,q2);
        p  = fmaf(qb[14],k3.z,p); q2 = fmaf(qb[15],k3.w,q2);
        float d0b = p + q2;
        float4 k4 = *(const float4*)(kp + 16);
        float4 k5 = *(const float4*)(kp + 20);
        float4 k6 = *(const float4*)(kp + 24);
        float4 k7 = *(const float4*)(kp + 28);
        p  = qb[16]*k4.x;          q2 = qb[17]*k4.y;
        p  = fmaf(qb[18],k4.z,p);  q2 = fmaf(qb[19],k4.w,q2);
        p  = fmaf(qb[20],k5.x,p);  q2 = fmaf(qb[21],k5.y,q2);
        p  = fmaf(qb[22],k5.z,p);  q2 = fmaf(qb[23],k5.w,q2);
        p  = fmaf(qb[24],k6.x,p);  q2 = fmaf(qb[25],k6.y,q2);
        p  = fmaf(qb[26],k6.z,p);  q2 = fmaf(qb[27],k6.w,q2);
        p  = fmaf(qb[28],k7.x,p);  q2 = fmaf(qb[29],k7.y,q2);
        p  = fmaf(qb[30],k7.z,p);  q2 = fmaf(qb[31],k7.w,q2);
        float d1b = p + q2;
        float p0b = __expf(d0b), p1b = __expf(d1b);
        l0b += p0b; l1b += p1b;
        const float* vp = sV + r1 * KVS;
        #pragma unroll
        for (int g = 0; g < 4; g++) {
            float4 vv = *(const float4*)(vp + 4 * g);
            ab[4*g]   = fmaf(p0b, vv.x, ab[4*g]);
            ab[4*g+1] = fmaf(p0b, vv.y, ab[4*g+1]);
            ab[4*g+2] = fmaf(p0b, vv.z, ab[4*g+2]);
            ab[4*g+3] = fmaf(p0b, vv.w, ab[4*g+3]);
        }
        #pragma unroll
        for (int g = 4; g < 8; g++) {
            float4 vv = *(const float4*)(vp + 4 * g);
            ab[4*g]   = fmaf(p1b, vv.x, ab[4*g]);
            ab[4*g+1] = fmaf(p1b, vv.y, ab[4*g+1]);
            ab[4*g+2] = fmaf(p1b, vv.z, ab[4*g+2]);
            ab[4*g+3] = fmaf(p1b, vv.w, ab[4*g+3]);
        }
        (void)r;
    }

    {
        float i0a = 1.f / l0a, i1a = 1.f / l1a;
        float i0b = 1.f / l0b, i1b = 1.f / l1b;
        #pragma unroll
        for (int j = 0; j < 16; j++) { aa[j] *= i0a; ab[j] *= i0b; }
        #pragma unroll
        for (int j = 16; j < 32; j++) { aa[j] *= i1a; ab[j] *= i1b; }
    }

    // ---- recompute LN1(x) for the residual (x is L2-resident) ----
    {
        const float4* pa = (const float4*)(gx + (gb * T + r0) * DM);
        const float4* pb = (const float4*)(gx + (gb * T + r1) * DM);
        #pragma unroll
        for (int i = 0; i < 8; i++) {
            float4 v = pa[i]; xa[4*i] = v.x; xa[4*i+1] = v.y; xa[4*i+2] = v.z; xa[4*i+3] = v.w;
            float4 w = pb[i]; xb[4*i] = w.x; xb[4*i+1] = w.y; xb[4*i+2] = w.z; xb[4*i+3] = w.w;
        }
        ln_row(xa, sg1, sbe1);
        ln_row(xb, sg1, sbe1);
    }

    // ---- attn @ Wo + bo + residual ----
    float x1a[DM], x1b[DM];
    #pragma unroll
    for (int dg = 0; dg < 8; dg++) {
        float a0=0.f,a1=0.f,a2=0.f,a3=0.f, b0=0.f,b1v=0.f,b2v=0.f,b3=0.f;
        #pragma unroll
        for (int e = 0; e < DM; e++) {
            float4 w = *(const float4*)(sWo + e * 32 + dg * 4);
            a0 = fmaf(aa[e], w.x, a0); a1  = fmaf(aa[e], w.y, a1);
            a2 = fmaf(aa[e], w.z, a2); a3  = fmaf(aa[e], w.w, a3);
            b0 = fmaf(ab[e], w.x, b0); b1v = fmaf(ab[e], w.y, b1v);
            b2v= fmaf(ab[e], w.z, b2v); b3 = fmaf(ab[e], w.w, b3);
        }
        x1a[4*dg]   = xa[4*dg]   + a0 + sbo[4*dg];
        x1a[4*dg+1] = xa[4*dg+1] + a1 + sbo[4*dg+1];
        x1a[4*dg+2] = xa[4*dg+2] + a2 + sbo[4*dg+2];
        x1a[4*dg+3] = xa[4*dg+3] + a3 + sbo[4*dg+3];
        x1b[4*dg]   = xb[4*dg]   + b0 + sbo[4*dg];
        x1b[4*dg+1] = xb[4*dg+1] + b1v+ sbo[4*dg+1];
        x1b[4*dg+2] = xb[4*dg+2] + b2v+ sbo[4*dg+2];
        x1b[4*dg+3] = xb[4*dg+3] + b3 + sbo[4*dg+3];
    }

    // ---- LN2 (FFN residual wraps POST-LN2 x) ----
    ln_row(x1a, sg2, sbe2);
    ln_row(x1b, sg2, sbe2);

    __syncthreads();   // W1 staged

    // ---- FFN, hidden fused ----
    float ra[DM], rb[DM];
    #pragma unroll
    for (int d = 0; d < DM; d++) { ra[d] = x1a[d] + sb2[d]; rb[d] = x1b[d] + sb2[d]; }

    for (int j0 = 0; j0 < FF; j0 += 4) {
        float h0a = sb1[j0], h1a = sb1[j0+1], h2a = sb1[j0+2], h3a = sb1[j0+3];
        float h0b = h0a, h1b = h1a, h2b = h2a, h3b = h3a;
        #pragma unroll
        for (int d = 0; d < DM; d++) {
            float4 w = *(const float4*)(sW1 + d * FF + j0);
            h0a = fmaf(x1a[d], w.x, h0a); h1a = fmaf(x1a[d], w.y, h1a);
            h2a = fmaf(x1a[d], w.z, h2a); h3a = fmaf(x1a[d], w.w, h3a);
            h0b = fmaf(x1b[d], w.x, h0b); h1b = fmaf(x1b[d], w.y, h1b);
            h2b = fmaf(x1b[d], w.z, h2b); h3b = fmaf(x1b[d], w.w, h3b);
        }
        h0a = fmaxf(h0a, 0.f); h1a = fmaxf(h1a, 0.f); h2a = fmaxf(h2a, 0.f); h3a = fmaxf(h3a, 0.f);
        h0b = fmaxf(h0b, 0.f); h1b = fmaxf(h1b, 0.f); h2b = fmaxf(h2b, 0.f); h3b = fmaxf(h3b, 0.f);
        #pragma unroll
        for (int dg = 0; dg < 8; dg++) {
            float4 w0 = *(const float4*)(sW2 + (j0 + 0) * 32 + dg * 4);
            float4 w1 = *(const float4*)(sW2 + (j0 + 1) * 32 + dg * 4);
            float4 w2 = *(const float4*)(sW2 + (j0 + 2) * 32 + dg * 4);
            float4 w3 = *(const float4*)(sW2 + (j0 + 3) * 32 + dg * 4);
            float r0v = ra[4*dg], r1v = ra[4*dg+1], r2v = ra[4*dg+2], r3v = ra[4*dg+3];
            r0v = fmaf(h0a, w0.x, r0v); r1v = fmaf(h0a, w0.y, r1v); r2v = fmaf(h0a, w0.z, r2v); r3v = fmaf(h0a, w0.w, r3v);
            r0v = fmaf(h1a, w1.x, r0v); r1v = fmaf(h1a, w1.y, r1v); r2v = fmaf(h1a, w1.z, r2v); r3v = fmaf(h1a, w1.w, r3v);
            r0v = fmaf(h2a, w2.x, r0v); r1v = fmaf(h2a, w2.y, r1v); r2v = fmaf(h2a, w2.z, r2v); r3v = fmaf(h2a, w2.w, r3v);
            r0v = fmaf(h3a, w3.x, r0v); r1v = fmaf(h3a, w3.y, r1v); r2v = fmaf(h3a, w3.z, r2v); r3v = fmaf(h3a, w3.w, r3v);
            ra[4*dg] = r0v; ra[4*dg+1] = r1v; ra[4*dg+2] = r2v; ra[4*dg+3] = r3v;
            float s0 = rb[4*dg], s1 = rb[4*dg+1], s2 = rb[4*dg+2], s3 = rb[4*dg+3];
            s0 = fmaf(h0b, w0.x, s0); s1 = fmaf(h0b, w0.y, s1); s2 = fmaf(h0b, w0.z, s2); s3 = fmaf(h0b, w0.w, s3);
            s0 = fmaf(h1b, w1.x, s0); s1 = fmaf(h1b, w1.y, s1); s2 = fmaf(h1b, w1.z, s2); s3 = fmaf(h1b, w1.w, s3);
            s0 = fmaf(h2b, w2.x, s0); s1 = fmaf(h2b, w2.y, s1); s2 = fmaf(h2b, w2.z, s2); s3 = fmaf(h2b, w2.w, s3);
            s0 = fmaf(h3b, w3.x, s0); s1 = fmaf(h3b, w3.y, s1); s2 = fmaf(h3b, w3.z, s2); s3 = fmaf(h3b, w3.w, s3);
            rb[4*dg] = s0; rb[4*dg+1] = s1; rb[4*dg+2] = s2; rb[4*dg+3] = s3;
        }
    }

    // ---- store both rows ----
    float4* oa = (float4*)(gout + (gb * T + r0) * DM);
    float4* ob = (float4*)(gout + (gb * T + r1) * DM);
    #pragma unroll
    for (int i = 0; i < 8; i++) {
        oa[i] = make_float4(ra[4*i], ra[4*i+1], ra[4*i+2], ra[4*i+3]);
        ob[i] = make_float4(rb[4*i], rb[4*i+1], rb[4*i+2], rb[4*i+3]);
    }
}

extern "C" void kernel_launch(void* const* d_in, const int* in_sizes, int n_in,
                              void* d_out, int out_size)
{
    const float* x   = (const float*)d_in[0];
    const float* Wq  = (const float*)d_in[1];
    const float* Wk  = (const float*)d_in[2];
    const float* Wv  = (const float*)d_in[3];
    const float* Wo  = (const float*)d_in[4];
    const float* bo  = (const float*)d_in[5];
    const float* W1  = (const float*)d_in[6];
    const float* b1  = (const float*)d_in[7];
    const float* W2  = (const float*)d_in[8];
    const float* b2  = (const float*)d_in[9];
    const float* g1  = (const float*)d_in[10];
    const float* be1 = (const float*)d_in[11];
    const float* g2  = (const float*)d_in[12];
    const float* be2 = (const float*)d_in[13];
    float* out = (float*)d_out;

    cudaFuncSetAttribute(block_kernel, cudaFuncAttributeMaxDynamicSharedMemorySize, SMEM_BYTES);
    block_kernel<<<Bsz / 2, 128, SMEM_BYTES>>>(x, Wq, Wk, Wv, Wo, bo, W1, b1, W2, b2,
                                               g1, be1, g2, be2, out);
}

// round 5
// speedup vs baseline: 1.0598x; 1.0598x over previous
#include <cuda_runtime.h>

// Fused transformer block with packed f32x2 FMA and anti-diagonal causal balancing.
// B=2048, T=128, DM=32, H=2, DK=16.
// CTA = 128 threads = 2 batch elements x 64 threads; thread u handles rows (u, 127-u).
// grid = 1024.

typedef unsigned long long u64;

namespace {
constexpr int Bsz = 2048;
constexpr int T   = 128;
constexpr int DM  = 32;
constexpr int KVS = 36;   // K/V row stride in floats (144B: 16B-aligned, reads broadcast)

// shared layout (floats)
constexpr int OFF_A  = 0;       // 4096: phase A = Wq|Wk|Wv (3072), phase B = W1 (4096)
constexpr int OFF_W2 = 4096;    // 4096
constexpr int OFF_WO = 8192;    // 1024
constexpr int OFF_B  = 9216;    // 320: bo[32] b1[128] b2[32] g1[32] be1[32] g2[32] be2[32]
constexpr int OFF_KV = 9536;    // 2 halves * (K 4608 + V 4608) = 18432
constexpr int SMEM_FLOATS = OFF_KV + 2 * 2 * T * KVS;   // 27968
constexpr int SMEM_BYTES  = SMEM_FLOATS * 4;            // 111872 -> 2 CTAs/SM
}

// ---- packed f32x2 helpers ----
__device__ __forceinline__ void ffma2(u64& acc, u64 a, u64 b) {
    asm("fma.rn.f32x2 %0, %1, %2, %0;" : "+l"(acc) : "l"(a), "l"(b));
}
__device__ __forceinline__ u64 bcast2(float x) {
    u64 r; unsigned xi = __float_as_uint(x);
    asm("mov.b64 %0, {%1, %1};" : "=l"(r) : "r"(xi));
    return r;
}
__device__ __forceinline__ u64 pk2(float lo, float hi) {
    u64 r; unsigned a = __float_as_uint(lo), b = __float_as_uint(hi);
    asm("mov.b64 %0, {%1, %2};" : "=l"(r) : "r"(a), "r"(b));
    return r;
}
__device__ __forceinline__ float2 unpk(u64 v) {
    unsigned lo, hi;
    asm("mov.b64 {%0, %1}, %2;" : "=r"(lo), "=r"(hi) : "l"(v));
    return make_float2(__uint_as_float(lo), __uint_as_float(hi));
}

__device__ __forceinline__ void ln_row(float* x, const float* g, const float* be) {
    float mu = 0.f;
    #pragma unroll
    for (int d = 0; d < DM; d++) mu += x[d];
    mu *= (1.f / DM);
    float var = 0.f;
    #pragma unroll
    for (int d = 0; d < DM; d++) { float c = x[d] - mu; var = fmaf(c, c, var); }
    var *= (1.f / DM);
    float r = rsqrtf(var + 1e-5f);
    #pragma unroll
    for (int d = 0; d < DM; d++) x[d] = (x[d] - mu) * r * g[d] + be[d];
}

// 16-dim dot of packed q pairs (8 u64) against k pairs (4 ulonglong2)
__device__ __forceinline__ float dot16(const u64* q2, const ulonglong2* kv) {
    u64 s0 = 0, s1 = 0;
    #pragma unroll
    for (int t = 0; t < 4; t++) { ffma2(s0, q2[2*t], kv[t].x); ffma2(s1, q2[2*t+1], kv[t].y); }
    float2 a = unpk(s0), b = unpk(s1);
    return (a.x + a.y) + (b.x + b.y);
}

// acc[0..15] += P0*v[pairs 0..7], P1*v[pairs 8..15]
__device__ __forceinline__ void vacc(u64* acc, u64 P0, u64 P1, const ulonglong2* vv) {
    #pragma unroll
    for (int t = 0; t < 4; t++) { ffma2(acc[2*t],   P0, vv[t].x);   ffma2(acc[2*t+1],   P0, vv[t].y); }
    #pragma unroll
    for (int t = 0; t < 4; t++) { ffma2(acc[8+2*t], P1, vv[4+t].x); ffma2(acc[8+2*t+1], P1, vv[4+t].y); }
}

// projection: out[16 pairs] per row; W layout [h][d][j] (2x32x16)
__device__ __forceinline__ void proj2(const float* W, const float* xa, const float* xb,
                                      u64* oa, u64* ob) {
    #pragma unroll 4
    for (int d = 0; d < 32; d++) {
        u64 ma = bcast2(xa[d]), mb = bcast2(xb[d]);
        const ulonglong2* w0 = (const ulonglong2*)(W + d * 16);
        const ulonglong2* w1 = (const ulonglong2*)(W + 512 + d * 16);
        #pragma unroll
        for (int t = 0; t < 4; t++) {
            ulonglong2 wv = w0[t];
            ffma2(oa[2*t],   ma, wv.x); ffma2(oa[2*t+1],   ma, wv.y);
            ffma2(ob[2*t],   mb, wv.x); ffma2(ob[2*t+1],   mb, wv.y);
        }
        #pragma unroll
        for (int t = 0; t < 4; t++) {
            ulonglong2 wv = w1[t];
            ffma2(oa[8+2*t], ma, wv.x); ffma2(oa[8+2*t+1], ma, wv.y);
            ffma2(ob[8+2*t], mb, wv.x); ffma2(ob[8+2*t+1], mb, wv.y);
        }
    }
}

__global__ void __launch_bounds__(128, 2) block_kernel(
    const float* __restrict__ gx,
    const float* __restrict__ gWq, const float* __restrict__ gWk, const float* __restrict__ gWv,
    const float* __restrict__ gWo, const float* __restrict__ gbo,
    const float* __restrict__ gW1, const float* __restrict__ gb1,
    const float* __restrict__ gW2, const float* __restrict__ gb2,
    const float* __restrict__ gg1, const float* __restrict__ gbe1,
    const float* __restrict__ gg2, const float* __restrict__ gbe2,
    float* __restrict__ gout)
{
    extern __shared__ float sm[];
    float* sA   = sm + OFF_A;      // QKV then W1
    float* sW2  = sm + OFF_W2;
    float* sWo  = sm + OFF_WO;
    float* sbo  = sm + OFF_B;
    float* sb1  = sm + OFF_B + 32;
    float* sb2  = sm + OFF_B + 160;
    float* sg1  = sm + OFF_B + 192;
    float* sbe1 = sm + OFF_B + 224;
    float* sg2  = sm + OFF_B + 256;
    float* sbe2 = sm + OFF_B + 288;

    const int tid  = threadIdx.x;
    const int wid  = tid >> 5;
    const int lane = tid & 31;
    const int half = wid >> 1;              // local batch 0/1
    const int uw   = wid & 1;               // warp within half
    const int u    = (uw << 5) | lane;      // 0..63
    const int ra   = u;                     // row a
    const int rb   = 127 - u;               // row b
    const long gb  = (long)blockIdx.x * 2 + half;

    float* sK = sm + OFF_KV + half * (2 * T * KVS);
    float* sV = sK + T * KVS;

    // ---- phase A cooperative loads: QKV (region A), Wo, W2, biases ----
    {
        float4*       dq = (float4*)sA;
        const float4* s;
        s = (const float4*)gWq; for (int i = tid; i < 256;  i += 128) dq[i]       = s[i];
        s = (const float4*)gWk; for (int i = tid; i < 256;  i += 128) dq[256 + i] = s[i];
        s = (const float4*)gWv; for (int i = tid; i < 256;  i += 128) dq[512 + i] = s[i];
        float4* d2 = (float4*)sW2; s = (const float4*)gW2; for (int i = tid; i < 1024; i += 128) d2[i] = s[i];
        float4* d3 = (float4*)sWo; s = (const float4*)gWo; for (int i = tid; i < 256;  i += 128) d3[i] = s[i];
        if (tid < 32) {
            sbo[tid]  = gbo[tid];  sb2[tid]  = gb2[tid];
            sg1[tid]  = gg1[tid];  sbe1[tid] = gbe1[tid];
            sg2[tid]  = gg2[tid];  sbe2[tid] = gbe2[tid];
        }
        sb1[tid] = gb1[tid];
    }
    __syncthreads();

    // ---- x rows + LN1 ----
    float xa[DM], xb[DM];
    {
        const float4* pa = (const float4*)(gx + (gb * T + ra) * DM);
        const float4* pb = (const float4*)(gx + (gb * T + rb) * DM);
        #pragma unroll
        for (int i = 0; i < 8; i++) {
            float4 v = pa[i]; xa[4*i] = v.x; xa[4*i+1] = v.y; xa[4*i+2] = v.z; xa[4*i+3] = v.w;
            float4 w = pb[i]; xb[4*i] = w.x; xb[4*i+1] = w.y; xb[4*i+2] = w.z; xb[4*i+3] = w.w;
        }
        ln_row(xa, sg1, sbe1);
        ln_row(xb, sg1, sbe1);
    }

    // ---- projections (packed pairs over output j) ----
    u64 qa2[16], qb2[16];
    #pragma unroll
    for (int p = 0; p < 16; p++) { qa2[p] = 0; qb2[p] = 0; }
    proj2(sA, xa, xb, qa2, qb2);

    {
        u64 ka2[16], kb2[16];
        #pragma unroll
        for (int p = 0; p < 16; p++) { ka2[p] = 0; kb2[p] = 0; }
        proj2(sA + 1024, xa, xb, ka2, kb2);
        u64* krA = (u64*)(sK + ra * KVS);
        u64* krB = (u64*)(sK + rb * KVS);
        #pragma unroll
        for (int p = 0; p < 16; p++) { krA[p] = ka2[p]; krB[p] = kb2[p]; }
    }
    {
        u64 va2[16], vb2[16];
        #pragma unroll
        for (int p = 0; p < 16; p++) { va2[p] = 0; vb2[p] = 0; }
        proj2(sA + 2048, xa, xb, va2, vb2);
        u64* vrA = (u64*)(sV + ra * KVS);
        u64* vrB = (u64*)(sV + rb * KVS);
        #pragma unroll
        for (int p = 0; p < 16; p++) { vrA[p] = va2[p]; vrB[p] = vb2[p]; }
    }
    __syncthreads();   // K/V visible; region A free

    // stage W1 into region A (consumed after next barrier, overlapped with attention)
    {
        const float4* s = (const float4*)gW1;
        float4*       d = (float4*)sA;
        for (int i = tid; i < 1024; i += 128) d[i] = s[i];
    }

    // ---- causal attention: rows (u, 127-u); warp-uniform phase bounds ----
    u64 aa2[16], ab2[16];
    #pragma unroll
    for (int p = 0; p < 16; p++) { aa2[p] = 0; ab2[p] = 0; }
    float l0a = 0.f, l1a = 0.f, l0b = 0.f, l1b = 0.f;

    const int wa_max = (uw << 5) + 31;    // last s where any lane's row-a is active
    const int wb_max = 127 - (uw << 5);   // last s where any lane's row-b is active (>= wa_max)

    for (int s = 0; s <= wb_max; s++) {
        const ulonglong2* kp = (const ulonglong2*)(sK + s * KVS);
        ulonglong2 kv[8];
        #pragma unroll
        for (int t = 0; t < 8; t++) kv[t] = kp[t];

        // row b scores (always)
        float d0b = dot16(qb2, kv);
        float d1b = dot16(qb2 + 8, kv + 4);
        float p0b = (s <= rb) ? __expf(d0b) : 0.f;
        float p1b = (s <= rb) ? __expf(d1b) : 0.f;
        l0b += p0b; l1b += p1b;

        bool actA = (s <= wa_max);
        float p0a = 0.f, p1a = 0.f;
        if (actA) {
            float d0a = dot16(qa2, kv);
            float d1a = dot16(qa2 + 8, kv + 4);
            p0a = (s <= ra) ? __expf(d0a) : 0.f;
            p1a = (s <= ra) ? __expf(d1a) : 0.f;
            l0a += p0a; l1a += p1a;
        }

        const ulonglong2* vp = (const ulonglong2*)(sV + s * KVS);
        ulonglong2 vv[8];
        #pragma unroll
        for (int t = 0; t < 8; t++) vv[t] = vp[t];

        vacc(ab2, bcast2(p0b), bcast2(p1b), vv);
        if (actA) vacc(aa2, bcast2(p0a), bcast2(p1a), vv);
    }

    // normalize -> scalar attention outputs
    float ata[DM], atb[DM];
    {
        float i0a = 1.f / l0a, i1a = 1.f / l1a;
        float i0b = 1.f / l0b, i1b = 1.f / l1b;
        #pragma unroll
        for (int p = 0; p < 8; p++) {
            float2 f = unpk(aa2[p]); ata[2*p] = f.x * i0a; ata[2*p+1] = f.y * i0a;
            float2 g = unpk(ab2[p]); atb[2*p] = g.x * i0b; atb[2*p+1] = g.y * i0b;
        }
        #pragma unroll
        for (int p = 8; p < 16; p++) {
            float2 f = unpk(aa2[p]); ata[2*p] = f.x * i1a; ata[2*p+1] = f.y * i1a;
            float2 g = unpk(ab2[p]); atb[2*p] = g.x * i1b; atb[2*p+1] = g.y * i1b;
        }
    }

    // ---- attn @ Wo (packed) ----
    u64 oa2[16], ob2[16];
    #pragma unroll
    for (int p = 0; p < 16; p++) { oa2[p] = 0; ob2[p] = 0; }
    #pragma unroll 4
    for (int e = 0; e < 32; e++) {
        u64 ma = bcast2(ata[e]), mb = bcast2(atb[e]);
        const ulonglong2* wp = (const ulonglong2*)(sWo + e * 32);
        #pragma unroll
        for (int t = 0; t < 8; t++) {
            ulonglong2 wv = wp[t];
            ffma2(oa2[2*t], ma, wv.x); ffma2(oa2[2*t+1], ma, wv.y);
            ffma2(ob2[2*t], mb, wv.x); ffma2(ob2[2*t+1], mb, wv.y);
        }
    }

    // ---- residual (recompute LN1 from x in L2) + bo, then LN2 ----
    float x2a[DM], x2b[DM];
    {
        const float4* pa = (const float4*)(gx + (gb * T + ra) * DM);
        const float4* pb = (const float4*)(gx + (gb * T + rb) * DM);
        #pragma unroll
        for (int i = 0; i < 8; i++) {
            float4 v = pa[i]; x2a[4*i] = v.x; x2a[4*i+1] = v.y; x2a[4*i+2] = v.z; x2a[4*i+3] = v.w;
            float4 w = pb[i]; x2b[4*i] = w.x; x2b[4*i+1] = w.y; x2b[4*i+2] = w.z; x2b[4*i+3] = w.w;
        }
        ln_row(x2a, sg1, sbe1);
        ln_row(x2b, sg1, sbe1);
        #pragma unroll
        for (int p = 0; p < 16; p++) {
            float2 f = unpk(oa2[p]);
            x2a[2*p]   += f.x + sbo[2*p];
            x2a[2*p+1] += f.y + sbo[2*p+1];
            float2 g = unpk(ob2[p]);
            x2b[2*p]   += g.x + sbo[2*p];
            x2b[2*p+1] += g.y + sbo[2*p+1];
        }
        ln_row(x2a, sg2, sbe2);
        ln_row(x2b, sg2, sbe2);
    }

    __syncthreads();   // W1 fully staged

    // ---- FFN: res = x2 + b2 + relu(x2@W1 + b1)@W2 ----
    u64 ra2[16], rb2[16];
    #pragma unroll
    for (int p = 0; p < 16; p++) {
        ra2[p] = pk2(x2a[2*p] + sb2[2*p], x2a[2*p+1] + sb2[2*p+1]);
        rb2[p] = pk2(x2b[2*p] + sb2[2*p], x2b[2*p+1] + sb2[2*p+1]);
    }

    for (int blk = 0; blk < 8; blk++) {
        const int j0 = blk * 16;
        u64 ha[8], hb[8];
        #pragma unroll
        for (int p = 0; p < 8; p++) { ha[p] = 0; hb[p] = 0; }
        #pragma unroll 4
        for (int d = 0; d < 32; d++) {
            u64 ma = bcast2(x2a[d]), mb = bcast2(x2b[d]);
            const ulonglong2* wp = (const ulonglong2*)(sA + d * 128 + j0);
            #pragma unroll
            for (int t = 0; t < 4; t++) {
                ulonglong2 wv = wp[t];
                ffma2(ha[2*t], ma, wv.x); ffma2(ha[2*t+1], ma, wv.y);
                ffma2(hb[2*t], mb, wv.x); ffma2(hb[2*t+1], mb, wv.y);
            }
        }
        #pragma unroll
        for (int p = 0; p < 8; p++) {
            const int j = j0 + 2 * p;
            float2 fa = unpk(ha[p]), fb = unpk(hb[p]);
            float h0a = fmaxf(fa.x + sb1[j],     0.f);
            float h1a = fmaxf(fa.y + sb1[j + 1], 0.f);
            float h0b = fmaxf(fb.x + sb1[j],     0.f);
            float h1b = fmaxf(fb.y + sb1[j + 1], 0.f);
            u64 Pa0 = bcast2(h0a), Pa1 = bcast2(h1a);
            u64 Pb0 = bcast2(h0b), Pb1 = bcast2(h1b);
            const ulonglong2* w2a = (const ulonglong2*)(sW2 + j * 32);
            const ulonglong2* w2b = (const ulonglong2*)(sW2 + (j + 1) * 32);
            #pragma unroll
            for (int t = 0; t < 8; t++) {
                ulonglong2 wv = w2a[t];
                ffma2(ra2[2*t],   Pa0, wv.x); ffma2(ra2[2*t+1],   Pa0, wv.y);
                ffma2(rb2[2*t],   Pb0, wv.x); ffma2(rb2[2*t+1],   Pb0, wv.y);
            }
            #pragma unroll
            for (int t = 0; t < 8; t++) {
                ulonglong2 wv = w2b[t];
                ffma2(ra2[2*t],   Pa1, wv.x); ffma2(ra2[2*t+1],   Pa1, wv.y);
                ffma2(rb2[2*t],   Pb1, wv.x); ffma2(rb2[2*t+1],   Pb1, wv.y);
            }
        }
    }

    // ---- store both rows ----
    ulonglong2* oA = (ulonglong2*)(gout + (gb * T + ra) * DM);
    ulonglong2* oB = (ulonglong2*)(gout + (gb * T + rb) * DM);
    #pragma unroll
    for (int t = 0; t < 8; t++) {
        oA[t] = make_ulonglong2(ra2[2*t], ra2[2*t+1]);
        oB[t] = make_ulonglong2(rb2[2*t], rb2[2*t+1]);
    }
}

extern "C" void kernel_launch(void* const* d_in, const int* in_sizes, int n_in,
                              void* d_out, int out_size)
{
    const float* x   = (const float*)d_in[0];
    const float* Wq  = (const float*)d_in[1];
    const float* Wk  = (const float*)d_in[2];
    const float* Wv  = (const float*)d_in[3];
    const float* Wo  = (const float*)d_in[4];
    const float* bo  = (const float*)d_in[5];
    const float* W1  = (const float*)d_in[6];
    const float* b1  = (const float*)d_in[7];
    const float* W2  = (const float*)d_in[8];
    const float* b2  = (const float*)d_in[9];
    const float* g1  = (const float*)d_in[10];
    const float* be1 = (const float*)d_in[11];
    const float* g2  = (const float*)d_in[12];
    const float* be2 = (const float*)d_in[13];
    float* out = (float*)d_out;

    cudaFuncSetAttribute(block_kernel, cudaFuncAttributeMaxDynamicSharedMemorySize, SMEM_BYTES);
    block_kernel<<<Bsz / 2, 128, SMEM_BYTES>>>(x, Wq, Wk, Wv, Wo, bo, W1, b1, W2, b2,
                                               g1, be1, g2, be2, out);
}

// round 6
// speedup vs baseline: 1.1425x; 1.0780x over previous
#include <cuda_runtime.h>

// Fused transformer block. B=2048, T=128, DM=32, H=2, DK=16.
// CTA = 256 threads = 2 batches x (64 anti-diagonal row pairs x 2 heads).
// Attention: thread (hb,h,u) handles rows (u,127-u) for head h. FFN: 1 row/thread.
// Packed fma.rn.f32x2 throughout. grid = 1024.

typedef unsigned long long u64;

namespace {
constexpr int Bsz = 2048;
constexpr int T   = 128;
constexpr int DM  = 32;
constexpr int KVS = 36;   // K/V row stride in floats (144B, 16B-aligned)

// shared layout (floats)
constexpr int OFF_A  = 0;       // 4096: phase A = Wq|Wk|Wv (3072), phase B = W1 (4096)
constexpr int OFF_W2 = 4096;    // 4096
constexpr int OFF_WO = 8192;    // 1024
constexpr int OFF_B  = 9216;    // 320: bo[32] b1[128] b2[32] g1[32] be1[32] g2[32] be2[32]
constexpr int OFF_KV = 9536;    // 2 batches * (K 4608 + V 4608)
constexpr int SMEM_FLOATS = OFF_KV + 2 * 2 * T * KVS;   // 27968
constexpr int SMEM_BYTES  = SMEM_FLOATS * 4;            // 111872 -> 2 CTAs/SM
}

// ---- packed f32x2 helpers ----
__device__ __forceinline__ void ffma2(u64& acc, u64 a, u64 b) {
    asm("fma.rn.f32x2 %0, %1, %2, %0;" : "+l"(acc) : "l"(a), "l"(b));
}
__device__ __forceinline__ u64 bcast2(float x) {
    u64 r; unsigned xi = __float_as_uint(x);
    asm("mov.b64 %0, {%1, %1};" : "=l"(r) : "r"(xi));
    return r;
}
__device__ __forceinline__ u64 pk2(float lo, float hi) {
    u64 r; unsigned a = __float_as_uint(lo), b = __float_as_uint(hi);
    asm("mov.b64 %0, {%1, %2};" : "=l"(r) : "r"(a), "r"(b));
    return r;
}
__device__ __forceinline__ float2 unpk(u64 v) {
    unsigned lo, hi;
    asm("mov.b64 {%0, %1}, %2;" : "=r"(lo), "=r"(hi) : "l"(v));
    return make_float2(__uint_as_float(lo), __uint_as_float(hi));
}

__device__ __forceinline__ void ln_row(float* x, const float* g, const float* be) {
    float mu = 0.f;
    #pragma unroll
    for (int d = 0; d < DM; d++) mu += x[d];
    mu *= (1.f / DM);
    float var = 0.f;
    #pragma unroll
    for (int d = 0; d < DM; d++) { float c = x[d] - mu; var = fmaf(c, c, var); }
    var *= (1.f / DM);
    float r = rsqrtf(var + 1e-5f);
    #pragma unroll
    for (int d = 0; d < DM; d++) x[d] = (x[d] - mu) * r * g[d] + be[d];
}

// one-head projection for two rows: W is [32 d][16 j], outputs 8 pairs per row
__device__ __forceinline__ void proj_h(const float* __restrict__ W,
                                       const float* __restrict__ xa,
                                       const float* __restrict__ xb,
                                       u64* oa, u64* ob) {
    #pragma unroll 8
    for (int d = 0; d < 32; d++) {
        u64 ma = bcast2(xa[d]), mb = bcast2(xb[d]);
        const ulonglong2* wp = (const ulonglong2*)(W + d * 16);
        #pragma unroll
        for (int t = 0; t < 4; t++) {
            ulonglong2 wv = wp[t];
            ffma2(oa[2*t],   ma, wv.x); ffma2(oa[2*t+1],   ma, wv.y);
            ffma2(ob[2*t],   mb, wv.x); ffma2(ob[2*t+1],   mb, wv.y);
        }
    }
}

// 16-dim dot against k tile already in regs
__device__ __forceinline__ float dot8r(const u64* q2, const ulonglong2* kv) {
    u64 s0 = 0, s1 = 0;
    #pragma unroll
    for (int t = 0; t < 4; t++) { ffma2(s0, q2[2*t], kv[t].x); ffma2(s1, q2[2*t+1], kv[t].y); }
    float2 a = unpk(s0), b = unpk(s1);
    return (a.x + a.y) + (b.x + b.y);
}

__global__ void __launch_bounds__(256, 2) block_kernel(
    const float* __restrict__ gx,
    const float* __restrict__ gWq, const float* __restrict__ gWk, const float* __restrict__ gWv,
    const float* __restrict__ gWo, const float* __restrict__ gbo,
    const float* __restrict__ gW1, const float* __restrict__ gb1,
    const float* __restrict__ gW2, const float* __restrict__ gb2,
    const float* __restrict__ gg1, const float* __restrict__ gbe1,
    const float* __restrict__ gg2, const float* __restrict__ gbe2,
    float* __restrict__ gout)
{
    extern __shared__ float sm[];
    float* sA   = sm + OFF_A;      // QKV then W1
    float* sW2  = sm + OFF_W2;
    float* sWo  = sm + OFF_WO;
    float* sbo  = sm + OFF_B;
    float* sb1  = sm + OFF_B + 32;
    float* sb2  = sm + OFF_B + 160;
    float* sg1  = sm + OFF_B + 192;
    float* sbe1 = sm + OFF_B + 224;
    float* sg2  = sm + OFF_B + 256;
    float* sbe2 = sm + OFF_B + 288;

    const int tid = threadIdx.x;
    const int hb  = tid >> 7;             // local batch 0/1
    const int t7  = tid & 127;
    const int h   = t7 >> 6;              // head 0/1
    const int u   = t7 & 63;              // 0..63 (warp-contiguous in 0-31 / 32-63)
    const int ra  = u;
    const int rb  = 127 - u;
    const long gb = (long)blockIdx.x * 2 + hb;

    float* sK = sm + OFF_KV + hb * (2 * T * KVS);
    float* sV = sK + T * KVS;

    // ---- phase A cooperative loads ----
    {
        float4*       dq = (float4*)sA;
        const float4* s;
        s = (const float4*)gWq; for (int i = tid; i < 256;  i += 256) dq[i]       = s[i];
        s = (const float4*)gWk; for (int i = tid; i < 256;  i += 256) dq[256 + i] = s[i];
        s = (const float4*)gWv; for (int i = tid; i < 256;  i += 256) dq[512 + i] = s[i];
        float4* d2 = (float4*)sW2; s = (const float4*)gW2; for (int i = tid; i < 1024; i += 256) d2[i] = s[i];
        float4* d3 = (float4*)sWo; s = (const float4*)gWo; for (int i = tid; i < 256;  i += 256) d3[i] = s[i];
        if (tid < 32) {
            sbo[tid]  = gbo[tid];  sb2[tid]  = gb2[tid];
            sg1[tid]  = gg1[tid];  sbe1[tid] = gbe1[tid];
            sg2[tid]  = gg2[tid];  sbe2[tid] = gbe2[tid];
        }
        if (tid < 128) sb1[tid] = gb1[tid];
    }
    __syncthreads();

    // ---- x rows + LN1 (both head-threads of a row duplicate this; cheap) ----
    float xa[DM], xb[DM];
    {
        const float4* pa = (const float4*)(gx + (gb * T + ra) * DM);
        const float4* pb = (const float4*)(gx + (gb * T + rb) * DM);
        #pragma unroll
        for (int i = 0; i < 8; i++) {
            float4 v = pa[i]; xa[4*i] = v.x; xa[4*i+1] = v.y; xa[4*i+2] = v.z; xa[4*i+3] = v.w;
            float4 w = pb[i]; xb[4*i] = w.x; xb[4*i+1] = w.y; xb[4*i+2] = w.z; xb[4*i+3] = w.w;
        }
        ln_row(xa, sg1, sbe1);
        ln_row(xb, sg1, sbe1);
    }

    // ---- projections for head h only: k, v (stored), then q (kept live) ----
    {
        u64 k2a[8], k2b[8];
        #pragma unroll
        for (int p = 0; p < 8; p++) { k2a[p] = 0; k2b[p] = 0; }
        proj_h(sA + 1024 + h * 512, xa, xb, k2a, k2b);
        u64* krA = (u64*)(sK + ra * KVS + h * 16);
        u64* krB = (u64*)(sK + rb * KVS + h * 16);
        #pragma unroll
        for (int p = 0; p < 8; p++) { krA[p] = k2a[p]; krB[p] = k2b[p]; }
    }
    {
        u64 v2a[8], v2b[8];
        #pragma unroll
        for (int p = 0; p < 8; p++) { v2a[p] = 0; v2b[p] = 0; }
        proj_h(sA + 2048 + h * 512, xa, xb, v2a, v2b);
        u64* vrA = (u64*)(sV + ra * KVS + h * 16);
        u64* vrB = (u64*)(sV + rb * KVS + h * 16);
        #pragma unroll
        for (int p = 0; p < 8; p++) { vrA[p] = v2a[p]; vrB[p] = v2b[p]; }
    }
    u64 qa2[8], qb2[8];
    #pragma unroll
    for (int p = 0; p < 8; p++) { qa2[p] = 0; qb2[p] = 0; }
    proj_h(sA + h * 512, xa, xb, qa2, qb2);

    __syncthreads();   // K/V visible; QKV weights dead

    // stage W1 into region A (overlaps attention; consumed after later barriers)
    {
        const float4* s = (const float4*)gW1;
        float4*       d = (float4*)sA;
        #pragma unroll
        for (int i = tid; i < 1024; i += 256) d[i] = s[i];
    }

    // ---- attention: rows (u,127-u), head h; two warp-uniform segments ----
    u64 aa2[8], ab2[8];
    #pragma unroll
    for (int p = 0; p < 8; p++) { aa2[p] = 0; ab2[p] = 0; }
    float la = 0.f, lb = 0.f;

    const int ub     = u & 32;          // warp-uniform: 0 or 32
    const int wa_max = ub + 31;         // seg1 end (inclusive)
    const int wb_max = 127 - ub;        // seg2 end (inclusive)
    const float* kh = sK + h * 16;
    const float* vh = sV + h * 16;

    // segment 1: s = 0..wa_max — row a predicated per lane, row b always active
    for (int s = 0; s <= wa_max; s++) {
        const ulonglong2* kp = (const ulonglong2*)(kh + s * KVS);
        ulonglong2 kv[4];
        #pragma unroll
        for (int q = 0; q < 4; q++) kv[q] = kp[q];
        float da = dot8r(qa2, kv);
        float db = dot8r(qb2, kv);
        float pa = (s <= ra) ? __expf(da) : 0.f;
        float pb = __expf(db);
        la += pa; lb += pb;

        const ulonglong2* vp = (const ulonglong2*)(vh + s * KVS);
        ulonglong2 vv[4];
        #pragma unroll
        for (int q = 0; q < 4; q++) vv[q] = vp[q];
        u64 Pa = bcast2(pa), Pb = bcast2(pb);
        #pragma unroll
        for (int q = 0; q < 4; q++) {
            ffma2(aa2[2*q],   Pa, vv[q].x); ffma2(aa2[2*q+1],   Pa, vv[q].y);
            ffma2(ab2[2*q],   Pb, vv[q].x); ffma2(ab2[2*q+1],   Pb, vv[q].y);
        }
    }
    // segment 2: s = wa_max+1..wb_max — row b only, predicated per lane
    for (int s = wa_max + 1; s <= wb_max; s++) {
        const ulonglong2* kp = (const ulonglong2*)(kh + s * KVS);
        ulonglong2 kv[4];
        #pragma unroll
        for (int q = 0; q < 4; q++) kv[q] = kp[q];
        float db = dot8r(qb2, kv);
        float pb = (s <= rb) ? __expf(db) : 0.f;
        lb += pb;

        const ulonglong2* vp = (const ulonglong2*)(vh + s * KVS);
        u64 Pb = bcast2(pb);
        #pragma unroll
        for (int q = 0; q < 4; q++) {
            ulonglong2 vv = vp[q];
            ffma2(ab2[2*q], Pb, vv.x); ffma2(ab2[2*q+1], Pb, vv.y);
        }
    }

    __syncthreads();   // all K reads complete; K region becomes attn-out buffer

    // normalize and store attn outputs (head slice) into K region
    {
        float ia = 1.f / la, ib = 1.f / lb;
        u64* oA = (u64*)(sK + ra * KVS + h * 16);
        u64* oB = (u64*)(sK + rb * KVS + h * 16);
        #pragma unroll
        for (int p = 0; p < 8; p++) {
            float2 f = unpk(aa2[p]); oA[p] = pk2(f.x * ia, f.y * ia);
            float2 g = unpk(ab2[p]); oB[p] = pk2(g.x * ib, g.y * ib);
        }
    }
    __syncthreads();

    // ==== FFN phase: 1 row per thread (r = t7), same batch hb ====
    const int r = t7;

    // read full attn row
    float at[DM];
    {
        const u64* ap = (const u64*)(sK + r * KVS);
        #pragma unroll
        for (int p = 0; p < 16; p++) {
            float2 f = unpk(ap[p]); at[2*p] = f.x; at[2*p+1] = f.y;
        }
    }

    // attn @ Wo
    u64 o2[16];
    #pragma unroll
    for (int p = 0; p < 16; p++) o2[p] = 0;
    #pragma unroll 8
    for (int e = 0; e < 32; e++) {
        u64 m = bcast2(at[e]);
        const ulonglong2* wp = (const ulonglong2*)(sWo + e * 32);
        #pragma unroll
        for (int q = 0; q < 8; q++) {
            ulonglong2 wv = wp[q];
            ffma2(o2[2*q], m, wv.x); ffma2(o2[2*q+1], m, wv.y);
        }
    }

    // residual: recompute LN1(x_r) from gmem (L2-resident), add Wo out + bo, LN2
    float x2[DM];
    {
        const float4* pr = (const float4*)(gx + (gb * T + r) * DM);
        #pragma unroll
        for (int i = 0; i < 8; i++) {
            float4 v = pr[i]; x2[4*i] = v.x; x2[4*i+1] = v.y; x2[4*i+2] = v.z; x2[4*i+3] = v.w;
        }
        ln_row(x2, sg1, sbe1);
        #pragma unroll
        for (int p = 0; p < 16; p++) {
            float2 f = unpk(o2[p]);
            x2[2*p]   += f.x + sbo[2*p];
            x2[2*p+1] += f.y + sbo[2*p+1];
        }
        ln_row(x2, sg2, sbe2);
    }

    // FFN: res = x2 + b2 + relu(x2@W1 + b1) @ W2
    u64 r2[16];
    #pragma unroll
    for (int p = 0; p < 16; p++)
        r2[p] = pk2(x2[2*p] + sb2[2*p], x2[2*p+1] + sb2[2*p+1]);

    #pragma unroll 1
    for (int blk = 0; blk < 8; blk++) {
        const float* w1p = sA + blk * 16;   // W1 block of 16 hidden cols
        u64 hh[8];
        #pragma unroll
        for (int p = 0; p < 8; p++) hh[p] = 0;
        #pragma unroll 8
        for (int d = 0; d < 32; d++) {
            u64 m = bcast2(x2[d]);
            const ulonglong2* wp = (const ulonglong2*)(w1p + d * 128);
            #pragma unroll
            for (int q = 0; q < 4; q++) {
                ulonglong2 wv = wp[q];
                ffma2(hh[2*q], m, wv.x); ffma2(hh[2*q+1], m, wv.y);
            }
        }
        #pragma unroll
        for (int p = 0; p < 8; p++) {
            const int j = blk * 16 + 2 * p;
            float2 f = unpk(hh[p]);
            float h0 = fmaxf(f.x + sb1[j],     0.f);
            float h1 = fmaxf(f.y + sb1[j + 1], 0.f);
            u64 P0 = bcast2(h0), P1 = bcast2(h1);
            const ulonglong2* wA = (const ulonglong2*)(sW2 + j * 32);
            const ulonglong2* wB = (const ulonglong2*)(sW2 + (j + 1) * 32);
            #pragma unroll
            for (int q = 0; q < 8; q++) {
                ulonglong2 wv = wA[q];
                ffma2(r2[2*q], P0, wv.x); ffma2(r2[2*q+1], P0, wv.y);
            }
            #pragma unroll
            for (int q = 0; q < 8; q++) {
                ulonglong2 wv = wB[q];
                ffma2(r2[2*q], P1, wv.x); ffma2(r2[2*q+1], P1, wv.y);
            }
        }
    }

    // store row
    ulonglong2* op = (ulonglong2*)(gout + (gb * T + r) * DM);
    #pragma unroll
    for (int q = 0; q < 8; q++) op[q] = make_ulonglong2(r2[2*q], r2[2*q+1]);
}

extern "C" void kernel_launch(void* const* d_in, const int* in_sizes, int n_in,
                              void* d_out, int out_size)
{
    const float* x   = (const float*)d_in[0];
    const float* Wq  = (const float*)d_in[1];
    const float* Wk  = (const float*)d_in[2];
    const float* Wv  = (const float*)d_in[3];
    const float* Wo  = (const float*)d_in[4];
    const float* bo  = (const float*)d_in[5];
    const float* W1  = (const float*)d_in[6];
    const float* b1  = (const float*)d_in[7];
    const float* W2  = (const float*)d_in[8];
    const float* b2  = (const float*)d_in[9];
    const float* g1  = (const float*)d_in[10];
    const float* be1 = (const float*)d_in[11];
    const float* g2  = (const float*)d_in[12];
    const float* be2 = (const float*)d_in[13];
    float* out = (float*)d_out;

    cudaFuncSetAttribute(block_kernel, cudaFuncAttributeMaxDynamicSharedMemorySize, SMEM_BYTES);
    block_kernel<<<Bsz / 2, 256, SMEM_BYTES>>>(x, Wq, Wk, Wv, Wo, bo, W1, b1, W2, b2,
                                               g1, be1, g2, be2, out);
}

// round 9
// speedup vs baseline: 1.3314x; 1.1653x over previous
#include <cuda_runtime.h>

// Fused transformer block. B=2048, T=128, DM=32, H=2, DK=16.
// CTA = 256 threads, 2 batches. Attention: thread (hb,h,u) -> rows (u,127-u), head h.
// Post-attention: threads 0..127 each own row r for BOTH batches (cross-batch weight reuse).
// Packed fma.rn.f32x2 throughout. grid = 1024.

typedef unsigned long long u64;

namespace {
constexpr int Bsz = 2048;
constexpr int T   = 128;
constexpr int DM  = 32;
constexpr int KVS = 36;   // K/V row stride (floats)
constexpr int AST = 66;   // attn/x2 interleaved buffer row stride (floats): 64 data + 2 pad

// shared layout (floats)
constexpr int OFF_A  = 0;       // 4096: phase A = Wq|Wk|Wv (3072), phase B = W1 (4096)
constexpr int OFF_W2 = 4096;    // 4096
constexpr int OFF_WO = 8192;    // 1024
constexpr int OFF_B  = 9216;    // 320: bo[32] b1[128] b2[32] g1[32] be1[32] g2[32] be2[32]
constexpr int OFF_KV = 9536;    // 2 batches * (K 4608 + V 4608); attnbuf (128*66=8448) aliases it later
constexpr int SMEM_FLOATS = OFF_KV + 2 * 2 * T * KVS;   // 27968
constexpr int SMEM_BYTES  = SMEM_FLOATS * 4;            // 111872 -> 2 CTAs/SM
}

// ---- packed f32x2 helpers ----
__device__ __forceinline__ void ffma2(u64& acc, u64 a, u64 b) {
    asm("fma.rn.f32x2 %0, %1, %2, %0;" : "+l"(acc) : "l"(a), "l"(b));
}
__device__ __forceinline__ u64 bcast2(float x) {
    u64 r; unsigned xi = __float_as_uint(x);
    asm("mov.b64 %0, {%1, %1};" : "=l"(r) : "r"(xi));
    return r;
}
__device__ __forceinline__ u64 pk2(float lo, float hi) {
    u64 r; unsigned a = __float_as_uint(lo), b = __float_as_uint(hi);
    asm("mov.b64 %0, {%1, %2};" : "=l"(r) : "r"(a), "r"(b));
    return r;
}
__device__ __forceinline__ float2 unpk(u64 v) {
    unsigned lo, hi;
    asm("mov.b64 {%0, %1}, %2;" : "=r"(lo), "=r"(hi) : "l"(v));
    return make_float2(__uint_as_float(lo), __uint_as_float(hi));
}
// split a (b0,b1) pair into two broadcast pairs
__device__ __forceinline__ void split_bcast(u64 v, u64& m0, u64& m1) {
    unsigned lo, hi;
    asm("mov.b64 {%0, %1}, %2;" : "=r"(lo), "=r"(hi) : "l"(v));
    asm("mov.b64 %0, {%1, %1};" : "=l"(m0) : "r"(lo));
    asm("mov.b64 %0, {%1, %1};" : "=l"(m1) : "r"(hi));
}

__device__ __forceinline__ void ln_row(float* x, const float* g, const float* be) {
    float mu = 0.f;
    #pragma unroll
    for (int d = 0; d < DM; d++) mu += x[d];
    mu *= (1.f / DM);
    float var = 0.f;
    #pragma unroll
    for (int d = 0; d < DM; d++) { float c = x[d] - mu; var = fmaf(c, c, var); }
    var *= (1.f / DM);
    float r = rsqrtf(var + 1e-5f);
    #pragma unroll
    for (int d = 0; d < DM; d++) x[d] = (x[d] - mu) * r * g[d] + be[d];
}

// one-head projection for two rows: W is [32 d][16 j]
__device__ __forceinline__ void proj_h(const float* __restrict__ W,
                                       const float* __restrict__ xa,
                                       const float* __restrict__ xb,
                                       u64* oa, u64* ob) {
    #pragma unroll 8
    for (int d = 0; d < 32; d++) {
        u64 ma = bcast2(xa[d]), mb = bcast2(xb[d]);
        const ulonglong2* wp = (const ulonglong2*)(W + d * 16);
        #pragma unroll
        for (int t = 0; t < 4; t++) {
            ulonglong2 wv = wp[t];
            ffma2(oa[2*t],   ma, wv.x); ffma2(oa[2*t+1],   ma, wv.y);
            ffma2(ob[2*t],   mb, wv.x); ffma2(ob[2*t+1],   mb, wv.y);
        }
    }
}

__device__ __forceinline__ float dot8r(const u64* q2, const ulonglong2* kv) {
    u64 s0 = 0, s1 = 0;
    #pragma unroll
    for (int t = 0; t < 4; t++) { ffma2(s0, q2[2*t], kv[t].x); ffma2(s1, q2[2*t+1], kv[t].y); }
    float2 a = unpk(s0), b = unpk(s1);
    return (a.x + a.y) + (b.x + b.y);
}

__global__ void __launch_bounds__(256, 2) block_kernel(
    const float* __restrict__ gx,
    const float* __restrict__ gWq, const float* __restrict__ gWk, const float* __restrict__ gWv,
    const float* __restrict__ gWo, const float* __restrict__ gbo,
    const float* __restrict__ gW1, const float* __restrict__ gb1,
    const float* __restrict__ gW2, const float* __restrict__ gb2,
    const float* __restrict__ gg1, const float* __restrict__ gbe1,
    const float* __restrict__ gg2, const float* __restrict__ gbe2,
    float* __restrict__ gout)
{
    extern __shared__ float sm[];
    float* sA    = sm + OFF_A;      // QKV then W1
    float* sW2   = sm + OFF_W2;
    float* sWo   = sm + OFF_WO;
    float* sbo   = sm + OFF_B;
    float* sb1   = sm + OFF_B + 32;
    float* sb2   = sm + OFF_B + 160;
    float* sg1   = sm + OFF_B + 192;
    float* sbe1  = sm + OFF_B + 224;
    float* sg2   = sm + OFF_B + 256;
    float* sbe2  = sm + OFF_B + 288;
    float* attnF = sm + OFF_KV;     // phase >=5: interleaved attn/x2 buffer, 128 rows * AST

    const int tid = threadIdx.x;
    const int hb  = tid >> 7;             // local batch 0/1
    const int t7  = tid & 127;
    const int h   = t7 >> 6;              // head 0/1
    const int u   = t7 & 63;
    const int ra  = u;
    const int rb  = 127 - u;
    const long gb = (long)blockIdx.x * 2 + hb;

    float* sK = sm + OFF_KV + hb * (2 * T * KVS);
    float* sV = sK + T * KVS;

    // ---- phase A: cooperative weight loads ----
    {
        float4*       dq = (float4*)sA;
        const float4* s;
        s = (const float4*)gWq; for (int i = tid; i < 256;  i += 256) dq[i]       = s[i];
        s = (const float4*)gWk; for (int i = tid; i < 256;  i += 256) dq[256 + i] = s[i];
        s = (const float4*)gWv; for (int i = tid; i < 256;  i += 256) dq[512 + i] = s[i];
        float4* d2 = (float4*)sW2; s = (const float4*)gW2; for (int i = tid; i < 1024; i += 256) d2[i] = s[i];
        float4* d3 = (float4*)sWo; s = (const float4*)gWo; for (int i = tid; i < 256;  i += 256) d3[i] = s[i];
        if (tid < 32) {
            sbo[tid]  = gbo[tid];  sb2[tid]  = gb2[tid];
            sg1[tid]  = gg1[tid];  sbe1[tid] = gbe1[tid];
            sg2[tid]  = gg2[tid];  sbe2[tid] = gbe2[tid];
        }
        if (tid < 128) sb1[tid] = gb1[tid];
    }
    __syncthreads();

    // ---- x rows + LN1 ----
    float xa[DM], xb[DM];
    {
        const float4* pa = (const float4*)(gx + (gb * T + ra) * DM);
        const float4* pb = (const float4*)(gx + (gb * T + rb) * DM);
        #pragma unroll
        for (int i = 0; i < 8; i++) {
            float4 v = pa[i]; xa[4*i] = v.x; xa[4*i+1] = v.y; xa[4*i+2] = v.z; xa[4*i+3] = v.w;
            float4 w = pb[i]; xb[4*i] = w.x; xb[4*i+1] = w.y; xb[4*i+2] = w.z; xb[4*i+3] = w.w;
        }
        ln_row(xa, sg1, sbe1);
        ln_row(xb, sg1, sbe1);
    }

    // ---- head-h projections: k, v to smem; q kept live ----
    {
        u64 k2a[8], k2b[8];
        #pragma unroll
        for (int p = 0; p < 8; p++) { k2a[p] = 0; k2b[p] = 0; }
        proj_h(sA + 1024 + h * 512, xa, xb, k2a, k2b);
        u64* krA = (u64*)(sK + ra * KVS + h * 16);
        u64* krB = (u64*)(sK + rb * KVS + h * 16);
        #pragma unroll
        for (int p = 0; p < 8; p++) { krA[p] = k2a[p]; krB[p] = k2b[p]; }
    }
    {
        u64 v2a[8], v2b[8];
        #pragma unroll
        for (int p = 0; p < 8; p++) { v2a[p] = 0; v2b[p] = 0; }
        proj_h(sA + 2048 + h * 512, xa, xb, v2a, v2b);
        u64* vrA = (u64*)(sV + ra * KVS + h * 16);
        u64* vrB = (u64*)(sV + rb * KVS + h * 16);
        #pragma unroll
        for (int p = 0; p < 8; p++) { vrA[p] = v2a[p]; vrB[p] = v2b[p]; }
    }
    u64 qa2[8], qb2[8];
    #pragma unroll
    for (int p = 0; p < 8; p++) { qa2[p] = 0; qb2[p] = 0; }
    proj_h(sA + h * 512, xa, xb, qa2, qb2);

    __syncthreads();   // K/V visible; QKV weights dead

    // stage W1 into region A (overlaps attention)
    {
        const float4* s = (const float4*)gW1;
        float4*       d = (float4*)sA;
        #pragma unroll
        for (int i = tid; i < 1024; i += 256) d[i] = s[i];
    }

    // ---- attention: rows (u,127-u), head h; two warp-uniform segments ----
    u64 aa2[8], ab2[8];
    #pragma unroll
    for (int p = 0; p < 8; p++) { aa2[p] = 0; ab2[p] = 0; }
    float la = 0.f, lb = 0.f;

    const int ub     = u & 32;
    const int wa_max = ub + 31;
    const int wb_max = 127 - ub;
    const float* kh = sK + h * 16;
    const float* vh = sV + h * 16;

    for (int s = 0; s <= wa_max; s++) {
        const ulonglong2* kp = (const ulonglong2*)(kh + s * KVS);
        ulonglong2 kv[4];
        #pragma unroll
        for (int q = 0; q < 4; q++) kv[q] = kp[q];
        float da = dot8r(qa2, kv);
        float db = dot8r(qb2, kv);
        float pa = (s <= ra) ? __expf(da) : 0.f;
        float pb = __expf(db);
        la += pa; lb += pb;

        const ulonglong2* vp = (const ulonglong2*)(vh + s * KVS);
        ulonglong2 vv[4];
        #pragma unroll
        for (int q = 0; q < 4; q++) vv[q] = vp[q];
        u64 Pa = bcast2(pa), Pb = bcast2(pb);
        #pragma unroll
        for (int q = 0; q < 4; q++) {
            ffma2(aa2[2*q],   Pa, vv[q].x); ffma2(aa2[2*q+1],   Pa, vv[q].y);
            ffma2(ab2[2*q],   Pb, vv[q].x); ffma2(ab2[2*q+1],   Pb, vv[q].y);
        }
    }
    for (int s = wa_max + 1; s <= wb_max; s++) {
        const ulonglong2* kp = (const ulonglong2*)(kh + s * KVS);
        ulonglong2 kv[4];
        #pragma unroll
        for (int q = 0; q < 4; q++) kv[q] = kp[q];
        float db = dot8r(qb2, kv);
        float pb = (s <= rb) ? __expf(db) : 0.f;
        lb += pb;

        const ulonglong2* vp = (const ulonglong2*)(vh + s * KVS);
        u64 Pb = bcast2(pb);
        #pragma unroll
        for (int q = 0; q < 4; q++) {
            ulonglong2 vv = vp[q];
            ffma2(ab2[2*q], Pb, vv.x); ffma2(ab2[2*q+1], Pb, vv.y);
        }
    }

    __syncthreads();   // all K/V reads done; region becomes interleaved attn buffer

    // ---- store normalized attn, batch-interleaved: attnF[r*AST + 2*j + hb] ----
    {
        float ia = 1.f / la, ib = 1.f / lb;
        float* pA = attnF + ra * AST + hb;
        float* pB = attnF + rb * AST + hb;
        #pragma unroll
        for (int p = 0; p < 8; p++) {
            int j0 = 16 * h + 2 * p;
            float2 f = unpk(aa2[p]);
            pA[2*j0]       = f.x * ia;
            pA[2*(j0+1)]   = f.y * ia;
            float2 g = unpk(ab2[p]);
            pB[2*j0]       = g.x * ib;
            pB[2*(j0+1)]   = g.y * ib;
        }
    }
    __syncthreads();

    // ==== post-attention: threads 0..127, row t for BOTH batches ====
    if (tid >= 128) return;
    const int t = tid;
    const long gB0 = (long)blockIdx.x * 2;
    const long gB1 = gB0 + 1;

    // Wo accumulators initialized with residual LN1(x) + bo (x rows die before the loop)
    u64 oA[16], oB[16];
    {
        float xA[DM], xB[DM];
        const float4* p0 = (const float4*)(gx + (gB0 * T + t) * DM);
        const float4* p1 = (const float4*)(gx + (gB1 * T + t) * DM);
        #pragma unroll
        for (int i = 0; i < 8; i++) {
            float4 v = p0[i]; xA[4*i] = v.x; xA[4*i+1] = v.y; xA[4*i+2] = v.z; xA[4*i+3] = v.w;
            float4 w = p1[i]; xB[4*i] = w.x; xB[4*i+1] = w.y; xB[4*i+2] = w.z; xB[4*i+3] = w.w;
        }
        ln_row(xA, sg1, sbe1);
        ln_row(xB, sg1, sbe1);
        #pragma unroll
        for (int p = 0; p < 16; p++) {
            oA[p] = pk2(xA[2*p] + sbo[2*p], xA[2*p+1] + sbo[2*p+1]);
            oB[p] = pk2(xB[2*p] + sbo[2*p], xB[2*p+1] + sbo[2*p+1]);
        }
    }

    // attn @ Wo, both batches share each Wo load
    const float* myrow = attnF + t * AST;
    #pragma unroll 4
    for (int e = 0; e < 32; e++) {
        u64 ap = *(const u64*)(myrow + 2 * e);
        u64 m0, m1; split_bcast(ap, m0, m1);
        const ulonglong2* wp = (const ulonglong2*)(sWo + e * 32);
        #pragma unroll
        for (int q = 0; q < 8; q++) {
            ulonglong2 wv = wp[q];
            ffma2(oA[2*q], m0, wv.x); ffma2(oA[2*q+1], m0, wv.y);
            ffma2(oB[2*q], m1, wv.x); ffma2(oB[2*q+1], m1, wv.y);
        }
    }

    // LN2, stash x2 pairs in smem (same row, in place), init FFN residual accumulators
    u64 r2a[16], r2b[16];
    {
        float x2A[DM], x2B[DM];
        #pragma unroll
        for (int p = 0; p < 16; p++) {
            float2 f = unpk(oA[p]); x2A[2*p] = f.x; x2A[2*p+1] = f.y;
            float2 g = unpk(oB[p]); x2B[2*p] = g.x; x2B[2*p+1] = g.y;
        }
        ln_row(x2A, sg2, sbe2);
        ln_row(x2B, sg2, sbe2);
        u64* xrow = (u64*)myrow;
        #pragma unroll
        for (int d = 0; d < 32; d++) xrow[d] = pk2(x2A[d], x2B[d]);
        #pragma unroll
        for (int p = 0; p < 16; p++) {
            r2a[p] = pk2(x2A[2*p] + sb2[2*p], x2A[2*p+1] + sb2[2*p+1]);
            r2b[p] = pk2(x2B[2*p] + sb2[2*p], x2B[2*p+1] + sb2[2*p+1]);
        }
    }

    // ---- FFN: hidden in blocks of 16; x2 pairs re-read from smem; weights shared 2 rows ----
    #pragma unroll 1
    for (int blk = 0; blk < 8; blk++) {
        const float* w1p = sA + blk * 16;
        u64 h0[8], h1[8];
        #pragma unroll
        for (int p = 0; p < 8; p++) { h0[p] = 0; h1[p] = 0; }
        #pragma unroll 4
        for (int d = 0; d < 32; d++) {
            u64 xp = *(const u64*)(myrow + 2 * d);
            u64 m0, m1; split_bcast(xp, m0, m1);
            const ulonglong2* wp = (const ulonglong2*)(w1p + d * 128);
            #pragma unroll
            for (int q = 0; q < 4; q++) {
                ulonglong2 wv = wp[q];
                ffma2(h0[2*q],   m0, wv.x); ffma2(h0[2*q+1],   m0, wv.y);
                ffma2(h1[2*q],   m1, wv.x); ffma2(h1[2*q+1],   m1, wv.y);
            }
        }
        #pragma unroll
        for (int p = 0; p < 8; p++) {
            const int j = blk * 16 + 2 * p;
            float2 f0 = unpk(h0[p]);
            float2 f1 = unpk(h1[p]);
            float A0 = fmaxf(f0.x + sb1[j],     0.f);
            float A1 = fmaxf(f0.y + sb1[j + 1], 0.f);
            float B0 = fmaxf(f1.x + sb1[j],     0.f);
            float B1 = fmaxf(f1.y + sb1[j + 1], 0.f);
            {
                u64 Pa = bcast2(A0), Pb = bcast2(B0);
                const ulonglong2* w2 = (const ulonglong2*)(sW2 + j * 32);
                #pragma unroll
                for (int q = 0; q < 8; q++) {
                    ulonglong2 wv = w2[q];
                    ffma2(r2a[2*q], Pa, wv.x); ffma2(r2a[2*q+1], Pa, wv.y);
                    ffma2(r2b[2*q], Pb, wv.x); ffma2(r2b[2*q+1], Pb, wv.y);
                }
            }
            {
                u64 Pa = bcast2(A1), Pb = bcast2(B1);
                const ulonglong2* w2 = (const ulonglong2*)(sW2 + (j + 1) * 32);
                #pragma unroll
                for (int q = 0; q < 8; q++) {
                    ulonglong2 wv = w2[q];
                    ffma2(r2a[2*q], Pa, wv.x); ffma2(r2a[2*q+1], Pa, wv.y);
                    ffma2(r2b[2*q], Pb, wv.x); ffma2(r2b[2*q+1], Pb, wv.y);
                }
            }
        }
    }

    // ---- store both batches' row t ----
    ulonglong2* o0 = (ulonglong2*)(gout + (gB0 * T + t) * DM);
    ulonglong2* o1 = (ulonglong2*)(gout + (gB1 * T + t) * DM);
    #pragma unroll
    for (int q = 0; q < 8; q++) {
        o0[q] = make_ulonglong2(r2a[2*q], r2a[2*q+1]);
        o1[q] = make_ulonglong2(r2b[2*q], r2b[2*q+1]);
    }
}

extern "C" void kernel_launch(void* const* d_in, const int* in_sizes, int n_in,
                              void* d_out, int out_size)
{
    const float* x   = (const float*)d_in[0];
    const float* Wq  = (const float*)d_in[1];
    const float* Wk  = (const float*)d_in[2];
    const float* Wv  = (const float*)d_in[3];
    const float* Wo  = (const float*)d_in[4];
    const float* bo  = (const float*)d_in[5];
    const float* W1  = (const float*)d_in[6];
    const float* b1  = (const float*)d_in[7];
    const float* W2  = (const float*)d_in[8];
    const float* b2  = (const float*)d_in[9];
    const float* g1  = (const float*)d_in[10];
    const float* be1 = (const float*)d_in[11];
    const float* g2  = (const float*)d_in[12];
    const float* be2 = (const float*)d_in[13];
    float* out = (float*)d_out;

    cudaFuncSetAttribute(block_kernel, cudaFuncAttributeMaxDynamicSharedMemorySize, SMEM_BYTES);
    block_kernel<<<Bsz / 2, 256, SMEM_BYTES>>>(x, Wq, Wk, Wv, Wo, bo, W1, b1, W2, b2,
                                               g1, be1, g2, be2, out);
}